// round 4
// baseline (speedup 1.0000x reference)
#include <cuda_runtime.h>
#include <cuda_bf16.h>
#include <math.h>
#include <stdint.h>

// ---------------- problem constants ----------------
#define LLn   144
#define DIN   1024
#define DT    150
#define DTP   160
#define NOUT  4
#define BL    288
#define BZO   1152
#define OI    600
#define NFLAT 90000          // OI*DT  (flattened op1 N)
#define OUT1N 23887872
#define PEROUT 5971968
#define TOT4   11943936

// ---------------- scratch (device globals, bf16 hi/lo splits) -------------
// NOTE: pad columns j in [150,160) of g_w are never written -> stay at their
// load-time zero-init, which is exactly what op2's K=160 needs.
__device__ __align__(256) __nv_bfloat16 g_xh[BL*DIN],        g_xl[BL*DIN];
__device__ __align__(256) __nv_bfloat16 g_Wph[4][DT*DIN],    g_Wpl[4][DT*DIN];   // [sel][n][k]
__device__ __align__(256) __nv_bfloat16 g_Wth[2][OI*DT*DTP], g_Wtl[2][OI*DT*DTP];// [tri][(oi,j)][k]
__device__ __align__(256) __nv_bfloat16 g_ph[4][BL*DTP],     g_pl[4][BL*DTP];
__device__ __align__(256) __nv_bfloat16 g_wh[(size_t)BZO*DT*DTP],  g_wl[(size_t)BZO*DT*DTP];
__device__ __align__(256) __nv_bfloat16 g_th[(size_t)BZO*LLn*DTP], g_tl[(size_t)BZO*LLn*DTP];

// ---------------- helpers ----------------
__device__ __forceinline__ void split2(float v, __nv_bfloat16& h, __nv_bfloat16& l) {
    h = __float2bfloat16_rn(v);
    l = __float2bfloat16_rn(v - __bfloat162float(h));
}

__device__ __forceinline__ uint32_t smem_u32(const void* p) {
    uint32_t a;
    asm("{ .reg .u64 t; cvta.to.shared.u64 t, %1; cvt.u32.u64 %0, t; }" : "=r"(a) : "l"(p));
    return a;
}

__device__ __forceinline__ void ldm4(uint32_t* d, uint32_t addr) {
    asm volatile("ldmatrix.sync.aligned.m8n8.x4.shared.b16 {%0,%1,%2,%3}, [%4];"
        : "=r"(d[0]), "=r"(d[1]), "=r"(d[2]), "=r"(d[3]) : "r"(addr));
}

__device__ __forceinline__ void mma_bf16(float* c, const uint32_t* a, uint32_t b0, uint32_t b1) {
    asm volatile("mma.sync.aligned.m16n8k16.row.col.f32.bf16.bf16.f32 "
        "{%0,%1,%2,%3}, {%4,%5,%6,%7}, {%8,%9}, {%0,%1,%2,%3};"
        : "+f"(c[0]), "+f"(c[1]), "+f"(c[2]), "+f"(c[3])
        : "r"(a[0]), "r"(a[1]), "r"(a[2]), "r"(a[3]), "r"(b0), "r"(b1));
}

__device__ __forceinline__ void cpa16(uint32_t dst, const void* src, uint32_t sz) {
    asm volatile("cp.async.cg.shared.global [%0], [%1], 16, %2;"
        :: "r"(dst), "l"(src), "r"(sz) : "memory");
}

// ---------------- prep kernels ----------------
__global__ void prep_x(const float* __restrict__ x) {
    int i = blockIdx.x * 256 + threadIdx.x;
    if (i >= BL * DIN) return;
    split2(x[i], g_xh[i], g_xl[i]);
}
__global__ void prep_pw(const float* __restrict__ W, int sel) {
    int i = blockIdx.x * 256 + threadIdx.x;
    if (i >= DT * DIN) return;
    int n = i >> 10, k = i & 1023;
    split2(__ldg(&W[k * DT + n]), g_Wph[sel][i], g_Wpl[sel][i]);
}
__global__ void prep_wt(const float* __restrict__ W, int tri) {
    __shared__ float t[32][33];
    int oi = blockIdx.x;
    int kt = blockIdx.y * 32, jt = blockIdx.z * 32;
    int tx = threadIdx.x, ty = threadIdx.y;
    int k = kt + ty, j = jt + tx;
    float v = (k < DT && j < DT) ? W[(size_t)oi * (DT * DT) + k * DT + j] : 0.f;
    t[ty][tx] = v;
    __syncthreads();
    int j2 = jt + ty, k2 = kt + tx;
    if (j2 < DT && k2 < DTP) {
        float u = t[tx][ty];
        size_t d = (size_t)oi * (DT * DTP) + (size_t)j2 * DTP + k2;
        split2(u, g_Wth[tri][d], g_Wtl[tri][d]);
    }
}

// ---------------- HMMA GEMM: BM=BN=64, BK=32, 256 threads, double-buffered -
// Tile layout in smem: [buf][mat][64 rows x 80B], mat 0=Ah 1=Al 2=Bh 3=Bl.
// MODE 0: proj   x(288x1024) @ Wp[z]^T(as [n][k])  -> g_p[z]  (z=blockIdx.z)
// MODE 1: op1    sh(288x150) @ Wt[tri] flat 90000  -> g_w
// MODE 2: op2    Y(144x150)  @ w[p] rows(i,k=j)    -> g_t
// MODE 3: op3/1  X(144x160)  @ t[p] rows(y,k=i)    -> out (direct)
// MODE 4: op3/2  same, transposed store
template<int MODE>
__global__ __launch_bounds__(256)
void tk(const float* __restrict__ b0s, const float* __restrict__ b1s,
        const float* __restrict__ b2s, const float* __restrict__ b3s,
        float* __restrict__ outp, int sel, int tri)
{
    __shared__ __align__(16) char sm[2][4][5120];

    const int tid  = threadIdx.x;
    const int lane = tid & 31, warp = tid >> 5;
    const int wm = warp >> 1, wn = warp & 1;
    const int bx = blockIdx.x, by = blockIdx.y, p = blockIdx.z;

    const __nv_bfloat16 *Ah, *Al, *Bh, *Bl;
    int pitchA, pitchB, KT, Mreal, NBreal;
    if constexpr (MODE == 0) {
        Ah = g_xh; Al = g_xl; Bh = g_Wph[p]; Bl = g_Wpl[p];
        pitchA = DIN; pitchB = DIN; KT = 32; Mreal = BL; NBreal = DT;
    }
    if constexpr (MODE == 1) {
        Ah = g_ph[0]; Al = g_pl[0];
        Bh = g_Wth[tri]; Bl = g_Wtl[tri];
        pitchA = DTP; pitchB = DTP; KT = 5; Mreal = BL; NBreal = NFLAT;
    }
    if constexpr (MODE == 2) {
        int b = p / 576;
        Ah = g_ph[sel] + (size_t)b * LLn * DTP; Al = g_pl[sel] + (size_t)b * LLn * DTP;
        Bh = g_wh + (size_t)p * DT * DTP;       Bl = g_wl + (size_t)p * DT * DTP;
        pitchA = DTP; pitchB = DTP; KT = 5; Mreal = LLn; NBreal = DT;
    }
    if constexpr (MODE >= 3) {
        int b = p / 576;
        Ah = g_ph[sel] + (size_t)b * LLn * DTP; Al = g_pl[sel] + (size_t)b * LLn * DTP;
        Bh = g_th + (size_t)p * LLn * DTP;      Bl = g_tl + (size_t)p * LLn * DTP;
        pitchA = DTP; pitchB = DTP; KT = 5; Mreal = LLn; NBreal = LLn;
    }

    const int m0 = bx * 64;
    const int n0 = by * 64;
    const uint32_t sbase = smem_u32(sm);

    // staging indices for this thread (one 16B segment in each of the 4 mats)
    const int srow = tid >> 2, sseg = tid & 3;
    const bool aValid = (m0 + srow) < Mreal;
    const bool bValid = (n0 + srow) < NBreal;
    const __nv_bfloat16* aSrcH = Ah + (size_t)(m0 + (aValid ? srow : 0)) * pitchA + sseg * 8;
    const __nv_bfloat16* aSrcL = Al + (size_t)(m0 + (aValid ? srow : 0)) * pitchA + sseg * 8;
    const __nv_bfloat16* bSrcH = Bh + (size_t)(n0 + (bValid ? srow : 0)) * pitchB + sseg * 8;
    const __nv_bfloat16* bSrcL = Bl + (size_t)(n0 + (bValid ? srow : 0)) * pitchB + sseg * 8;
    const uint32_t dOff = (uint32_t)(srow * 80 + sseg * 16);
    const uint32_t aSz = aValid ? 16u : 0u, bSz = bValid ? 16u : 0u;

    // ldmatrix lane offsets (pitch-80 rows, conflict-free)
    const int q = lane >> 3, r = lane & 7;
    const uint32_t aOff = (uint32_t)((wm * 16 + ((q & 1) ? 8 : 0) + r) * 80 + ((q >> 1) ? 16 : 0));
    const uint32_t bOff0 = (uint32_t)((wn * 32 + ((lane >> 4) ? 8 : 0) + r) * 80 + ((q & 1) ? 16 : 0));

    float acc[4][4];
    #pragma unroll
    for (int i = 0; i < 4; i++)
        #pragma unroll
        for (int j = 0; j < 4; j++) acc[i][j] = 0.f;

    // prefetch chunk 0
    {
        const int k0 = 0;
        cpa16(sbase + 0 * 5120 + dOff, aSrcH + k0, aSz);
        cpa16(sbase + 1 * 5120 + dOff, aSrcL + k0, aSz);
        cpa16(sbase + 2 * 5120 + dOff, bSrcH + k0, bSz);
        cpa16(sbase + 3 * 5120 + dOff, bSrcL + k0, bSz);
        asm volatile("cp.async.commit_group;" ::: "memory");
    }

    for (int ch = 0; ch < KT; ch++) {
        if (ch + 1 < KT) {
            const int k0 = (ch + 1) * 32;
            const uint32_t bb = (uint32_t)(((ch + 1) & 1) * 20480);
            cpa16(sbase + bb + 0 * 5120 + dOff, aSrcH + k0, aSz);
            cpa16(sbase + bb + 1 * 5120 + dOff, aSrcL + k0, aSz);
            cpa16(sbase + bb + 2 * 5120 + dOff, bSrcH + k0, bSz);
            cpa16(sbase + bb + 3 * 5120 + dOff, bSrcL + k0, bSz);
            asm volatile("cp.async.commit_group;" ::: "memory");
            asm volatile("cp.async.wait_group 1;" ::: "memory");
        } else {
            asm volatile("cp.async.wait_group 0;" ::: "memory");
        }
        __syncthreads();

        const uint32_t bb = (uint32_t)((ch & 1) * 20480);
        const uint32_t baseAh = sbase + bb,           baseAl = sbase + bb + 5120;
        const uint32_t baseBh = sbase + bb + 10240,   baseBl = sbase + bb + 15360;

        #pragma unroll
        for (int kk = 0; kk < 2; kk++) {
            const uint32_t ko = (uint32_t)(kk * 32);
            uint32_t ah[4], al4[4];
            ldm4(ah,  baseAh + aOff + ko);
            ldm4(al4, baseAl + aOff + ko);
            #pragma unroll
            for (int g = 0; g < 2; g++) {
                uint32_t bh[4], bl[4];
                const uint32_t bo = bOff0 + (uint32_t)(g * 16 * 80) + ko;
                ldm4(bh, baseBh + bo);
                ldm4(bl, baseBl + bo);
                mma_bf16(acc[2 * g],     ah,  bh[0], bh[1]);
                mma_bf16(acc[2 * g],     ah,  bl[0], bl[1]);
                mma_bf16(acc[2 * g],     al4, bh[0], bh[1]);
                mma_bf16(acc[2 * g + 1], ah,  bh[2], bh[3]);
                mma_bf16(acc[2 * g + 1], ah,  bl[2], bl[3]);
                mma_bf16(acc[2 * g + 1], al4, bh[2], bh[3]);
            }
        }
        __syncthreads();
    }

    // ---- store ----
    const float* bias = nullptr;
    if constexpr (MODE == 0)
        bias = (p == 0) ? b0s : (p == 1) ? b1s : (p == 2) ? b2s : b3s;

    const int g8 = lane >> 2, t2 = (lane & 3) * 2;
    const int mb = m0 + wm * 16, nb = n0 + wn * 32;
    #pragma unroll
    for (int j = 0; j < 4; j++) {
        #pragma unroll
        for (int e = 0; e < 4; e++) {
            const int m = mb + g8 + ((e >> 1) ? 8 : 0);
            const int n = nb + j * 8 + t2 + (e & 1);
            const float v = acc[j][e];
            if constexpr (MODE == 0) {
                if (m < BL && n < DTP) {
                    float val = (n < DT) ? v + bias[n] : 0.f;
                    size_t d = (size_t)m * DTP + n;
                    split2(val, g_ph[p][d], g_pl[p][d]);
                }
            }
            if constexpr (MODE == 1) {
                if (m < BL && n < NFLAT) {
                    int oi = n / DT, jj = n - oi * DT;
                    int o = oi / DT, i = oi - o * DT;
                    size_t d = ((size_t)(m * NOUT + o) * DT + i) * DTP + jj;
                    split2(v, g_wh[d], g_wl[d]);
                }
            }
            if constexpr (MODE == 2) {
                if (m < LLn && n < DTP) {
                    size_t d = ((size_t)p * LLn + m) * DTP + n;
                    split2(v, g_th[d], g_tl[d]);
                }
            }
            if constexpr (MODE == 3) {
                if (m < LLn && n < LLn) {
                    int bz = p >> 2, o = p & 3;
                    outp[(((size_t)bz * LLn + m) * LLn + n) * NOUT + o] = v;
                }
            }
            if constexpr (MODE == 4) {
                if (m < LLn && n < LLn) {
                    int bz = p >> 2, o = p & 3;
                    outp[(((size_t)bz * LLn + n) * LLn + m) * NOUT + o] = v;
                }
            }
        }
    }
}

// ---------------- epilogue: mask + log_softmax over NOUT=4 ----------------
__global__ void epilogue_kernel(float* __restrict__ out)
{
    int e = blockIdx.x * blockDim.x + threadIdx.x;
    if (e >= TOT4) return;
    int rr = e % PEROUT;
    int x = (rr / LLn) % LLn;
    int z = (rr / (LLn * LLn)) % LLn;

    float4* p4 = (float4*)out;
    float4 v = p4[e];
    if (z > x) {
        const float c = -1.3862943611198906f;
        v.x = c; v.y = c; v.z = c; v.w = c;
    } else {
        float m = fmaxf(fmaxf(v.x, v.y), fmaxf(v.z, v.w));
        float s = expf(v.x - m) + expf(v.y - m) + expf(v.z - m) + expf(v.w - m);
        float l = m + logf(s);
        v.x -= l; v.y -= l; v.z -= l; v.w -= l;
    }
    p4[e] = v;
}

// ---------------------------------------------------------------------------
extern "C" void kernel_launch(void* const* d_in, const int* in_sizes, int n_in,
                              void* d_out, int out_size)
{
    const float* x     = (const float*)d_in[0];
    const float* W_sh  = (const float*)d_in[1];
    const float* b_sh  = (const float*)d_in[2];
    const float* W_st  = (const float*)d_in[3];
    const float* b_st  = (const float*)d_in[4];
    const float* W_oh  = (const float*)d_in[5];
    const float* b_oh  = (const float*)d_in[6];
    const float* W_ot  = (const float*)d_in[7];
    const float* b_ot  = (const float*)d_in[8];
    const float* W_t1  = (const float*)d_in[9];
    const float* W_t2  = (const float*)d_in[10];
    float* out = (float*)d_out;

    // prep: split inputs/weights into bf16 hi/lo
    prep_x<<<(BL * DIN + 255) / 256, 256>>>(x);
    prep_pw<<<(DT * DIN + 255) / 256, 256>>>(W_sh, 0);
    prep_pw<<<(DT * DIN + 255) / 256, 256>>>(W_st, 1);
    prep_pw<<<(DT * DIN + 255) / 256, 256>>>(W_oh, 2);
    prep_pw<<<(DT * DIN + 255) / 256, 256>>>(W_ot, 3);
    prep_wt<<<dim3(OI, 5, 5), dim3(32, 32)>>>(W_t1, 0);
    prep_wt<<<dim3(OI, 5, 5), dim3(32, 32)>>>(W_t2, 1);

    // projections: M 5 tiles x N 3 tiles x 4 sel
    tk<0><<<dim3(5, 3, 4), 256>>>(b_sh, b_st, b_oh, b_ot, nullptr, 0, 0);

    // triaffine 1: (x=st[1], y=oh[2], z=sh[0], W1)
    tk<1><<<dim3(5, 1407, 1), 256>>>(nullptr, nullptr, nullptr, nullptr, nullptr, 0, 0);
    tk<2><<<dim3(3, 3, BZO),  256>>>(nullptr, nullptr, nullptr, nullptr, nullptr, 2, 0);
    tk<3><<<dim3(3, 3, BZO),  256>>>(nullptr, nullptr, nullptr, nullptr, out, 1, 0);

    // triaffine 2: (x=ot[3], y=st[1], z=sh[0], W2), transposed store
    tk<1><<<dim3(5, 1407, 1), 256>>>(nullptr, nullptr, nullptr, nullptr, nullptr, 0, 1);
    tk<2><<<dim3(3, 3, BZO),  256>>>(nullptr, nullptr, nullptr, nullptr, nullptr, 1, 0);
    tk<4><<<dim3(3, 3, BZO),  256>>>(nullptr, nullptr, nullptr, nullptr, out + OUT1N, 3, 0);

    // mask + log_softmax
    epilogue_kernel<<<(TOT4 + 255) / 256, 256>>>(out);
}

// round 5
// speedup vs baseline: 1.8183x; 1.8183x over previous
#include <cuda_runtime.h>
#include <cuda_bf16.h>
#include <math.h>
#include <stdint.h>

// ---------------- problem constants ----------------
#define LLn   144
#define DIN   1024
#define DT    150
#define DTP   160
#define NOUT  4
#define BL    288
#define BZO   1152
#define OI    600
#define NFLAT 90000          // OI*DT      (flattened op1 N)
#define NF2   86400          // 576*DT     (flattened op2 N per batch)
#define NF3   82944          // 576*LLn    (flattened op3 N per batch)
#define OUT1N 23887872
#define PEROUT 5971968
#define TOT4   11943936

// ---------------- scratch (device globals, bf16 hi/lo splits) -------------
// pad columns [150,160) of g_w / g_t are never written -> stay zero (load-time
// zero-init), which is exactly what the K=160 consumers need.
__device__ __align__(256) __nv_bfloat16 g_xh[BL*DIN],        g_xl[BL*DIN];
__device__ __align__(256) __nv_bfloat16 g_Wph[4][DT*DIN],    g_Wpl[4][DT*DIN];   // [sel][n][k]
__device__ __align__(256) __nv_bfloat16 g_Wth[2][OI*DT*DTP], g_Wtl[2][OI*DT*DTP];// [tri][(oi,j)][k]
__device__ __align__(256) __nv_bfloat16 g_ph[4][BL*DTP],     g_pl[4][BL*DTP];
__device__ __align__(256) __nv_bfloat16 g_wh[(size_t)BZO*DT*DTP],  g_wl[(size_t)BZO*DT*DTP];
__device__ __align__(256) __nv_bfloat16 g_th[(size_t)BZO*LLn*DTP], g_tl[(size_t)BZO*LLn*DTP];

// ---------------- helpers ----------------
__device__ __forceinline__ void split2(float v, __nv_bfloat16& h, __nv_bfloat16& l) {
    h = __float2bfloat16_rn(v);
    l = __float2bfloat16_rn(v - __bfloat162float(h));
}
__device__ __forceinline__ uint32_t smem_u32(const void* p) {
    uint32_t a;
    asm("{ .reg .u64 t; cvta.to.shared.u64 t, %1; cvt.u32.u64 %0, t; }" : "=r"(a) : "l"(p));
    return a;
}
__device__ __forceinline__ void ldm4(uint32_t* d, uint32_t addr) {
    asm volatile("ldmatrix.sync.aligned.m8n8.x4.shared.b16 {%0,%1,%2,%3}, [%4];"
        : "=r"(d[0]), "=r"(d[1]), "=r"(d[2]), "=r"(d[3]) : "r"(addr));
}
__device__ __forceinline__ void mma_bf16(float* c, const uint32_t* a, uint32_t b0, uint32_t b1) {
    asm volatile("mma.sync.aligned.m16n8k16.row.col.f32.bf16.bf16.f32 "
        "{%0,%1,%2,%3}, {%4,%5,%6,%7}, {%8,%9}, {%0,%1,%2,%3};"
        : "+f"(c[0]), "+f"(c[1]), "+f"(c[2]), "+f"(c[3])
        : "r"(a[0]), "r"(a[1]), "r"(a[2]), "r"(a[3]), "r"(b0), "r"(b1));
}
__device__ __forceinline__ void cpa16(uint32_t dst, const void* src, uint32_t sz) {
    asm volatile("cp.async.cg.shared.global [%0], [%1], 16, %2;"
        :: "r"(dst), "l"(src), "r"(sz) : "memory");
}

// ---------------- prep kernels ----------------
__global__ void prep_x(const float* __restrict__ x) {
    int i = blockIdx.x * 256 + threadIdx.x;
    if (i >= BL * DIN) return;
    split2(x[i], g_xh[i], g_xl[i]);
}
__global__ void prep_pw(const float* __restrict__ W, int sel) {
    int i = blockIdx.x * 256 + threadIdx.x;
    if (i >= DT * DIN) return;
    int n = i >> 10, k = i & 1023;
    split2(__ldg(&W[k * DT + n]), g_Wph[sel][i], g_Wpl[sel][i]);
}
__global__ void prep_wt(const float* __restrict__ W, int tri) {
    __shared__ float t[32][33];
    int oi = blockIdx.x;
    int kt = blockIdx.y * 32, jt = blockIdx.z * 32;
    int tx = threadIdx.x, ty = threadIdx.y;
    int k = kt + ty, j = jt + tx;
    float v = (k < DT && j < DT) ? W[(size_t)oi * (DT * DT) + k * DT + j] : 0.f;
    t[ty][tx] = v;
    __syncthreads();
    int j2 = jt + ty, k2 = kt + tx;
    if (j2 < DT && k2 < DTP) {
        float u = t[tx][ty];
        size_t d = (size_t)oi * (DT * DTP) + (size_t)j2 * DTP + k2;
        split2(u, g_Wth[tri][d], g_Wtl[tri][d]);
    }
}

// ---------------- HMMA GEMM: BM=48, BN=64, BK=32, 192 thr, double-buffered -
// smem per stage: Ah[48x80B] Al Bh[64x80B] Bl  = 17920B; 2 stages.
// MODE 0: proj   x(288x1024) @ Wp[z](as [n][k]) -> g_p[z]   (z=blockIdx.z)
// MODE 1: op1    sh(288xDTP) @ Wt[tri] flat N=90000 -> g_w
// MODE 2: op2    Y_b(144xDTP) @ g_w[b] flat N=86400 -> g_t  (z=b)
// MODE 3: op3/1  X_b(144xDTP) @ g_t[b] flat N=82944 -> out
// MODE 4: op3/2  same, transposed final coords
#define STG    17920
#define OFF_AL 3840
#define OFF_BH 7680
#define OFF_BL 12800

template<int MODE>
__global__ __launch_bounds__(192)
void tk(const float* __restrict__ b0s, const float* __restrict__ b1s,
        const float* __restrict__ b2s, const float* __restrict__ b3s,
        float* __restrict__ outp, int sel, int tri)
{
    __shared__ __align__(16) char sm[2][STG];

    const int tid  = threadIdx.x;
    const int lane = tid & 31, warp = tid >> 5;
    const int wm = warp >> 1, wn = warp & 1;
    const int bx = blockIdx.x, by = blockIdx.y, zb = blockIdx.z;
    const int m0 = bx * 48, n0 = by * 64;

    // triangular-mask block skip (outputs here are fully overwritten by epilogue)
    if constexpr (MODE == 3) {
        if (((n0 / LLn) >> 2) > m0 + 47) return;
    }
    if constexpr (MODE == 4) {
        int q0 = n0 / LLn, q1 = (n0 + 63) / LLn;
        int ymax = (q0 == q1) ? ((n0 + 63) % LLn) : (LLn - 1);
        if ((q0 >> 2) > ymax) return;
    }

    const __nv_bfloat16 *Ah, *Al, *Bh, *Bl;
    int pitchA, pitchB, KT, NB;
    if constexpr (MODE == 0) {
        Ah = g_xh; Al = g_xl; Bh = g_Wph[zb]; Bl = g_Wpl[zb];
        pitchA = DIN; pitchB = DIN; KT = 32; NB = DT;
    }
    if constexpr (MODE == 1) {
        Ah = g_ph[0]; Al = g_pl[0]; Bh = g_Wth[tri]; Bl = g_Wtl[tri];
        pitchA = DTP; pitchB = DTP; KT = 5; NB = NFLAT;
    }
    if constexpr (MODE == 2) {
        Ah = g_ph[sel] + (size_t)zb * LLn * DTP; Al = g_pl[sel] + (size_t)zb * LLn * DTP;
        Bh = g_wh + (size_t)zb * 576 * DT * DTP; Bl = g_wl + (size_t)zb * 576 * DT * DTP;
        pitchA = DTP; pitchB = DTP; KT = 5; NB = NF2;
    }
    if constexpr (MODE >= 3) {
        Ah = g_ph[sel] + (size_t)zb * LLn * DTP; Al = g_pl[sel] + (size_t)zb * LLn * DTP;
        Bh = g_th + (size_t)zb * 576 * LLn * DTP; Bl = g_tl + (size_t)zb * 576 * LLn * DTP;
        pitchA = DTP; pitchB = DTP; KT = 5; NB = NF3;
    }

    const uint32_t sbase = smem_u32(sm);

    // ---- staging: 896 16B segments/chunk (A: 2x192, B: 2x256) ----
    auto stageCh = [&](int ch) {
        const int k0 = ch * 32;
        const uint32_t sb = sbase + (uint32_t)((ch & 1) * STG);
        #pragma unroll
        for (int it = 0; it < 5; it++) {
            int idx = tid + it * 192;
            if (idx >= 896) break;
            int mat = (idx < 192) ? 0 : (idx < 384) ? 1 : (idx < 640) ? 2 : 3;
            int rem = idx - ((mat == 0) ? 0 : (mat == 1) ? 192 : (mat == 2) ? 384 : 640);
            int row = rem >> 2, seg = rem & 3;
            const __nv_bfloat16* src;
            uint32_t dst, szB;
            if (mat < 2) {
                src = (mat ? Al : Ah) + (size_t)(m0 + row) * pitchA + k0 + seg * 8;
                dst = sb + (uint32_t)(mat * OFF_AL + row * 80 + seg * 16);
                szB = 16;
            } else {
                int gr = n0 + row;
                bool v = gr < NB;
                if (!v) gr = n0;
                src = ((mat == 3) ? Bl : Bh) + (size_t)gr * pitchB + k0 + seg * 8;
                dst = sb + (uint32_t)(OFF_BH + (mat - 2) * 5120 + row * 80 + seg * 16);
                szB = v ? 16u : 0u;
            }
            cpa16(dst, src, szB);
        }
        asm volatile("cp.async.commit_group;" ::: "memory");
    };

    // ldmatrix lane offsets (pitch-80 rows, conflict-free)
    const int q = lane >> 3, r = lane & 7;
    const uint32_t aOff  = (uint32_t)((wm * 16 + ((q & 1) ? 8 : 0) + r) * 80 + ((q >> 1) ? 16 : 0));
    const uint32_t bOff0 = (uint32_t)((wn * 32 + ((lane >> 4) ? 8 : 0) + r) * 80 + ((q & 1) ? 16 : 0));

    float acc[4][4];
    #pragma unroll
    for (int i = 0; i < 4; i++)
        #pragma unroll
        for (int j = 0; j < 4; j++) acc[i][j] = 0.f;

    stageCh(0);

    for (int ch = 0; ch < KT; ch++) {
        if (ch + 1 < KT) {
            stageCh(ch + 1);
            asm volatile("cp.async.wait_group 1;" ::: "memory");
        } else {
            asm volatile("cp.async.wait_group 0;" ::: "memory");
        }
        __syncthreads();

        const uint32_t cb = sbase + (uint32_t)((ch & 1) * STG);
        #pragma unroll
        for (int ks = 0; ks < 2; ks++) {
            const uint32_t ko = (uint32_t)(ks * 32);
            uint32_t ah[4], al4[4];
            ldm4(ah,  cb + aOff + ko);
            ldm4(al4, cb + OFF_AL + aOff + ko);
            #pragma unroll
            for (int g = 0; g < 2; g++) {
                uint32_t bh[4], bl[4];
                const uint32_t bo = bOff0 + (uint32_t)(g * 1280) + ko;
                ldm4(bh, cb + OFF_BH + bo);
                ldm4(bl, cb + OFF_BL + bo);
                mma_bf16(acc[2 * g],     ah,  bh[0], bh[1]);
                mma_bf16(acc[2 * g],     ah,  bl[0], bl[1]);
                mma_bf16(acc[2 * g],     al4, bh[0], bh[1]);
                mma_bf16(acc[2 * g + 1], ah,  bh[2], bh[3]);
                mma_bf16(acc[2 * g + 1], ah,  bl[2], bl[3]);
                mma_bf16(acc[2 * g + 1], al4, bh[2], bh[3]);
            }
        }
        __syncthreads();
    }

    // ---- store ----
    const float* bias = nullptr;
    if constexpr (MODE == 0)
        bias = (zb == 0) ? b0s : (zb == 1) ? b1s : (zb == 2) ? b2s : b3s;

    const int g8 = lane >> 2, t2 = (lane & 3) * 2;
    const int mb = m0 + wm * 16, nbb = n0 + wn * 32;
    #pragma unroll
    for (int j = 0; j < 4; j++) {
        #pragma unroll
        for (int e = 0; e < 4; e++) {
            const int m = mb + g8 + ((e >> 1) ? 8 : 0);
            const int n = nbb + j * 8 + t2 + (e & 1);
            const float v = acc[j][e];
            if constexpr (MODE == 0) {
                if (n < DTP) {
                    float val = (n < DT) ? v + bias[n] : 0.f;
                    size_t d = (size_t)m * DTP + n;
                    split2(val, g_ph[zb][d], g_pl[zb][d]);
                }
            }
            if constexpr (MODE == 1) {
                if (n < NFLAT) {
                    int oi = n / DT, jj = n - oi * DT;
                    int o = oi / DT, i = oi - o * DT;
                    size_t d = ((size_t)(m * NOUT + o) * DT + i) * DTP + jj;
                    split2(v, g_wh[d], g_wl[d]);
                }
            }
            if constexpr (MODE == 2) {
                int qq = n / DT, i = n - qq * DT;
                size_t d = ((size_t)(zb * 576 + qq) * LLn + m) * DTP + i;
                split2(v, g_th[d], g_tl[d]);
            }
            if constexpr (MODE == 3) {
                int qq = n / LLn, y = n - qq * LLn;
                int z = qq >> 2, o = qq & 3;
                if (z <= m) {
                    size_t bz = (size_t)zb * LLn + z;
                    outp[((bz * LLn + m) * LLn + y) * NOUT + o] = v;
                }
            }
            if constexpr (MODE == 4) {
                int qq = n / LLn, y = n - qq * LLn;   // y = final x coord
                int z = qq >> 2, o = qq & 3;
                if (z <= y) {
                    size_t bz = (size_t)zb * LLn + z;
                    outp[((bz * LLn + y) * LLn + m) * NOUT + o] = v;
                }
            }
        }
    }
}

// ---------------- epilogue: mask + log_softmax over NOUT=4 ----------------
__global__ void epilogue_kernel(float* __restrict__ out)
{
    int e = blockIdx.x * blockDim.x + threadIdx.x;
    if (e >= TOT4) return;
    int rr = e % PEROUT;
    int x = (rr / LLn) % LLn;
    int z = (rr / (LLn * LLn)) % LLn;

    float4* p4 = (float4*)out;
    if (z > x) {
        const float c = -1.3862943611198906f;
        p4[e] = make_float4(c, c, c, c);
    } else {
        float4 v = p4[e];
        float m = fmaxf(fmaxf(v.x, v.y), fmaxf(v.z, v.w));
        float s = expf(v.x - m) + expf(v.y - m) + expf(v.z - m) + expf(v.w - m);
        float l = m + logf(s);
        v.x -= l; v.y -= l; v.z -= l; v.w -= l;
        p4[e] = v;
    }
}

// ---------------------------------------------------------------------------
extern "C" void kernel_launch(void* const* d_in, const int* in_sizes, int n_in,
                              void* d_out, int out_size)
{
    const float* x     = (const float*)d_in[0];
    const float* W_sh  = (const float*)d_in[1];
    const float* b_sh  = (const float*)d_in[2];
    const float* W_st  = (const float*)d_in[3];
    const float* b_st  = (const float*)d_in[4];
    const float* W_oh  = (const float*)d_in[5];
    const float* b_oh  = (const float*)d_in[6];
    const float* W_ot  = (const float*)d_in[7];
    const float* b_ot  = (const float*)d_in[8];
    const float* W_t1  = (const float*)d_in[9];
    const float* W_t2  = (const float*)d_in[10];
    float* out = (float*)d_out;

    // prep: split inputs/weights into bf16 hi/lo
    prep_x<<<(BL * DIN + 255) / 256, 256>>>(x);
    prep_pw<<<(DT * DIN + 255) / 256, 256>>>(W_sh, 0);
    prep_pw<<<(DT * DIN + 255) / 256, 256>>>(W_st, 1);
    prep_pw<<<(DT * DIN + 255) / 256, 256>>>(W_oh, 2);
    prep_pw<<<(DT * DIN + 255) / 256, 256>>>(W_ot, 3);
    prep_wt<<<dim3(OI, 5, 5), dim3(32, 32)>>>(W_t1, 0);
    prep_wt<<<dim3(OI, 5, 5), dim3(32, 32)>>>(W_t2, 1);

    // projections: M=288 (6 tiles) x N=150 (3 tiles of 64) x 4 sel
    tk<0><<<dim3(6, 3, 4), 192>>>(b_sh, b_st, b_oh, b_ot, nullptr, 0, 0);

    // triaffine 1: (x=st[1], y=oh[2], z=sh[0], W1)
    tk<1><<<dim3(6, 1407, 1), 192>>>(nullptr, nullptr, nullptr, nullptr, nullptr, 0, 0);
    tk<2><<<dim3(3, 1350, 2), 192>>>(nullptr, nullptr, nullptr, nullptr, nullptr, 2, 0);
    tk<3><<<dim3(3, 1296, 2), 192>>>(nullptr, nullptr, nullptr, nullptr, out, 1, 0);

    // triaffine 2: (x=ot[3], y=st[1], z=sh[0], W2), transposed final coords
    tk<1><<<dim3(6, 1407, 1), 192>>>(nullptr, nullptr, nullptr, nullptr, nullptr, 0, 1);
    tk<2><<<dim3(3, 1350, 2), 192>>>(nullptr, nullptr, nullptr, nullptr, nullptr, 1, 0);
    tk<4><<<dim3(3, 1296, 2), 192>>>(nullptr, nullptr, nullptr, nullptr, out + OUT1N, 3, 0);

    // mask + log_softmax
    epilogue_kernel<<<(TOT4 + 255) / 256, 256>>>(out);
}

// round 6
// speedup vs baseline: 2.5325x; 1.3928x over previous
#include <cuda_runtime.h>
#include <cuda_bf16.h>
#include <math.h>
#include <stdint.h>

// ---------------- problem constants ----------------
#define LLn   144
#define DIN   1024
#define DT    150
#define DTP   160
#define NOUT  4
#define BL    288
#define BZO   1152
#define OI    600
#define NFLAT 90000          // OI*DT      (flattened op1 N)
#define NF2   86400          // 576*DT     (flattened op2 N per batch)
#define NF3   82944          // 576*LLn    (flattened op3 N per batch)
#define OUT1N 23887872
#define PEROUT 5971968
#define TOT4   11943936

// ---------------- scratch (device globals, bf16 hi/lo splits) -------------
// pad columns [150,160) of g_w / g_t are never written -> stay zero (load-time
// zero-init), which is exactly what the K=160 consumers need.
__device__ __align__(256) __nv_bfloat16 g_xh[BL*DIN],        g_xl[BL*DIN];
__device__ __align__(256) __nv_bfloat16 g_Wph[4][DT*DIN],    g_Wpl[4][DT*DIN];   // [sel][n][k]
__device__ __align__(256) __nv_bfloat16 g_Wth[2][OI*DT*DTP], g_Wtl[2][OI*DT*DTP];// [tri][(oi,j)][k]
__device__ __align__(256) __nv_bfloat16 g_ph[4][BL*DTP],     g_pl[4][BL*DTP];
__device__ __align__(256) __nv_bfloat16 g_wh[(size_t)BZO*DT*DTP],  g_wl[(size_t)BZO*DT*DTP];
__device__ __align__(256) __nv_bfloat16 g_th[(size_t)BZO*LLn*DTP], g_tl[(size_t)BZO*LLn*DTP];

// ---------------- helpers ----------------
__device__ __forceinline__ void split2(float v, __nv_bfloat16& h, __nv_bfloat16& l) {
    h = __float2bfloat16_rn(v);
    l = __float2bfloat16_rn(v - __bfloat162float(h));
}
__device__ __forceinline__ void store_pair(__nv_bfloat16* baseH, __nv_bfloat16* baseL,
                                           size_t d, float v0, float v1) {
    __nv_bfloat16 h0, l0, h1, l1;
    split2(v0, h0, l0);
    split2(v1, h1, l1);
    uint32_t ph = (uint32_t)__bfloat16_as_ushort(h0) | ((uint32_t)__bfloat16_as_ushort(h1) << 16);
    uint32_t pl = (uint32_t)__bfloat16_as_ushort(l0) | ((uint32_t)__bfloat16_as_ushort(l1) << 16);
    *(uint32_t*)(baseH + d) = ph;
    *(uint32_t*)(baseL + d) = pl;
}
__device__ __forceinline__ uint32_t smem_u32(const void* p) {
    uint32_t a;
    asm("{ .reg .u64 t; cvta.to.shared.u64 t, %1; cvt.u32.u64 %0, t; }" : "=r"(a) : "l"(p));
    return a;
}
__device__ __forceinline__ void ldm4(uint32_t* d, uint32_t addr) {
    asm volatile("ldmatrix.sync.aligned.m8n8.x4.shared.b16 {%0,%1,%2,%3}, [%4];"
        : "=r"(d[0]), "=r"(d[1]), "=r"(d[2]), "=r"(d[3]) : "r"(addr));
}
__device__ __forceinline__ void mma_bf16(float* c, const uint32_t* a, uint32_t b0, uint32_t b1) {
    asm volatile("mma.sync.aligned.m16n8k16.row.col.f32.bf16.bf16.f32 "
        "{%0,%1,%2,%3}, {%4,%5,%6,%7}, {%8,%9}, {%0,%1,%2,%3};"
        : "+f"(c[0]), "+f"(c[1]), "+f"(c[2]), "+f"(c[3])
        : "r"(a[0]), "r"(a[1]), "r"(a[2]), "r"(a[3]), "r"(b0), "r"(b1));
}
__device__ __forceinline__ void cpa16(uint32_t dst, const void* src, uint32_t sz) {
    asm volatile("cp.async.cg.shared.global [%0], [%1], 16, %2;"
        :: "r"(dst), "l"(src), "r"(sz) : "memory");
}

// ---------------- prep kernels ----------------
__global__ void prep_x(const float* __restrict__ x) {
    int i = blockIdx.x * 256 + threadIdx.x;
    if (i >= BL * DIN) return;
    split2(x[i], g_xh[i], g_xl[i]);
}
__global__ void prep_pw(const float* __restrict__ W, int sel) {
    int i = blockIdx.x * 256 + threadIdx.x;
    if (i >= DT * DIN) return;
    int n = i >> 10, k = i & 1023;
    split2(__ldg(&W[k * DT + n]), g_Wph[sel][i], g_Wpl[sel][i]);
}
__global__ void prep_wt(const float* __restrict__ W, int tri) {
    __shared__ float t[32][33];
    int oi = blockIdx.x;
    int kt = blockIdx.y * 32, jt = blockIdx.z * 32;
    int tx = threadIdx.x, ty = threadIdx.y;
    int k = kt + ty, j = jt + tx;
    float v = (k < DT && j < DT) ? W[(size_t)oi * (DT * DT) + k * DT + j] : 0.f;
    t[ty][tx] = v;
    __syncthreads();
    int j2 = jt + ty, k2 = kt + tx;
    if (j2 < DT && k2 < DTP) {
        float u = t[tx][ty];
        size_t d = (size_t)oi * (DT * DTP) + (size_t)j2 * DTP + k2;
        split2(u, g_Wth[tri][d], g_Wtl[tri][d]);
    }
}

// ---------------- HMMA GEMM: BM=48, BN=96, BK=32, 192 thr, double-buffered -
// smem/stage: Ah[48x80B] Al Bh[96x80B] Bl = 23040B, 2 stages = 46080B.
// Warp grid 3(m) x 2(n): each warp 16m x 48n = 6 acc quads.
// MODE 0: proj   x(288x1024) @ Wp[z](as [n][k]) -> g_p[z]   (z=blockIdx.z)
// MODE 1: op1    sh(288xDTP) @ Wt[tri] flat N=90000 -> g_w
// MODE 2: op2    Y_b(144xDTP) @ g_w[b] flat N=86400 -> g_t  (z=b)
// MODE 3: op3/1  X_b(144xDTP) @ g_t[b] flat N=82944 -> out
// MODE 4: op3/2  same, transposed final coords
#define STG    23040
#define OFF_AL 3840
#define OFF_BH 7680
#define OFF_BL 15360
#define NIT    6            // 1152 segments / 192 threads

template<int MODE>
__global__ __launch_bounds__(192)
void tk(const float* __restrict__ b0s, const float* __restrict__ b1s,
        const float* __restrict__ b2s, const float* __restrict__ b3s,
        float* __restrict__ outp, int sel, int tri)
{
    __shared__ __align__(16) char sm[2][STG];

    const int tid  = threadIdx.x;
    const int lane = tid & 31, warp = tid >> 5;
    const int wm = warp >> 1, wn = warp & 1;
    const int bx = blockIdx.x, by = blockIdx.y, zb = blockIdx.z;
    const int m0 = bx * 48, n0 = by * 96;

    // triangular-mask block skip (skipped outputs are overwritten by epilogue)
    if constexpr (MODE == 3) {
        if (((n0 / LLn) >> 2) > m0 + 47) return;
    }
    if constexpr (MODE == 4) {
        int q0 = n0 / LLn, q1 = (n0 + 95) / LLn;
        int ymax = (q0 == q1) ? ((n0 + 95) % LLn) : (LLn - 1);
        if ((q0 >> 2) > ymax) return;
    }

    const __nv_bfloat16 *Ah, *Al, *Bh, *Bl;
    int pitchA, pitchB, KT, NB;
    if constexpr (MODE == 0) {
        Ah = g_xh; Al = g_xl; Bh = g_Wph[zb]; Bl = g_Wpl[zb];
        pitchA = DIN; pitchB = DIN; KT = 32; NB = DT;
    }
    if constexpr (MODE == 1) {
        Ah = g_ph[0]; Al = g_pl[0]; Bh = g_Wth[tri]; Bl = g_Wtl[tri];
        pitchA = DTP; pitchB = DTP; KT = 5; NB = NFLAT;
    }
    if constexpr (MODE == 2) {
        Ah = g_ph[sel] + (size_t)zb * LLn * DTP; Al = g_pl[sel] + (size_t)zb * LLn * DTP;
        Bh = g_wh + (size_t)zb * 576 * DT * DTP; Bl = g_wl + (size_t)zb * 576 * DT * DTP;
        pitchA = DTP; pitchB = DTP; KT = 5; NB = NF2;
    }
    if constexpr (MODE >= 3) {
        Ah = g_ph[sel] + (size_t)zb * LLn * DTP; Al = g_pl[sel] + (size_t)zb * LLn * DTP;
        Bh = g_th + (size_t)zb * 576 * LLn * DTP; Bl = g_tl + (size_t)zb * 576 * LLn * DTP;
        pitchA = DTP; pitchB = DTP; KT = 5; NB = NF3;
    }

    const uint32_t sbase = smem_u32(sm);

    // ---- precompute per-thread staging plan: NIT segments of 16B ----
    const __nv_bfloat16* sptr[NIT];
    uint32_t sdst[NIT], ssz[NIT];
    #pragma unroll
    for (int it = 0; it < NIT; it++) {
        int idx = tid + it * 192;                    // 0..1151
        if (idx < 384) {
            int mat = idx / 192;                     // 0=Ah 1=Al
            int rem = idx - mat * 192;
            int row = rem >> 2, seg = rem & 3;
            sptr[it] = (mat ? Al : Ah) + (size_t)(m0 + row) * pitchA + seg * 8;
            sdst[it] = (uint32_t)(mat * OFF_AL + row * 80 + seg * 16);
            ssz[it]  = 16;
        } else {
            int rem = idx - 384;                     // 0..767
            int mat = rem >> 9;                      // 0=Bh 1=Bl  (384 segs each)
            int brem = rem & 511;
            if (brem >= 384) { brem -= 384; mat = 1; }   // fold: rem 384..511 -> Bl low rows
            // remap: rem 0..383 Bh, 384..767 Bl
            mat = (rem < 384) ? 0 : 1;
            brem = (rem < 384) ? rem : rem - 384;
            int row = brem >> 2, seg = brem & 3;
            int gr = n0 + row;
            bool vv = gr < NB;
            sptr[it] = ((mat == 1) ? Bl : Bh) + (size_t)(vv ? gr : n0) * pitchB + seg * 8;
            sdst[it] = (uint32_t)(OFF_BH + mat * 7680 + row * 80 + seg * 16);
            ssz[it]  = vv ? 16u : 0u;
        }
    }

    // ---- ldmatrix lane offsets (pitch-80 rows, conflict-free) ----
    const int q = lane >> 3, r = lane & 7;
    const uint32_t aOff  = (uint32_t)((wm * 16 + ((q & 1) ? 8 : 0) + r) * 80 + ((q >> 1) ? 16 : 0));
    const uint32_t bOff0 = (uint32_t)((wn * 48 + ((lane >> 4) ? 8 : 0) + r) * 80 + ((q & 1) ? 16 : 0));

    float acc[6][4];
    #pragma unroll
    for (int i = 0; i < 6; i++)
        #pragma unroll
        for (int j = 0; j < 4; j++) acc[i][j] = 0.f;

    // stage chunk: fixed plan, pointers advance 32 elements per call
    auto stageCh = [&](int buf) {
        const uint32_t sb = sbase + (uint32_t)(buf * STG);
        #pragma unroll
        for (int it = 0; it < NIT; it++) {
            cpa16(sb + sdst[it], sptr[it], ssz[it]);
            sptr[it] += 32;
        }
        asm volatile("cp.async.commit_group;" ::: "memory");
    };

    stageCh(0);

    for (int ch = 0; ch < KT; ch++) {
        if (ch + 1 < KT) {
            stageCh((ch + 1) & 1);
            asm volatile("cp.async.wait_group 1;" ::: "memory");
        } else {
            asm volatile("cp.async.wait_group 0;" ::: "memory");
        }
        __syncthreads();

        const uint32_t cb = sbase + (uint32_t)((ch & 1) * STG);
        #pragma unroll
        for (int ks = 0; ks < 2; ks++) {
            const uint32_t ko = (uint32_t)(ks * 32);
            uint32_t ah[4], al4[4];
            ldm4(ah,  cb + aOff + ko);
            ldm4(al4, cb + OFF_AL + aOff + ko);
            #pragma unroll
            for (int g = 0; g < 3; g++) {
                uint32_t bh[4], bl[4];
                const uint32_t bo = bOff0 + (uint32_t)(g * 1280) + ko;
                ldm4(bh, cb + OFF_BH + bo);
                ldm4(bl, cb + OFF_BL + bo);
                mma_bf16(acc[2 * g],     ah,  bh[0], bh[1]);
                mma_bf16(acc[2 * g],     ah,  bl[0], bl[1]);
                mma_bf16(acc[2 * g],     al4, bh[0], bh[1]);
                mma_bf16(acc[2 * g + 1], ah,  bh[2], bh[3]);
                mma_bf16(acc[2 * g + 1], ah,  bl[2], bl[3]);
                mma_bf16(acc[2 * g + 1], al4, bh[2], bh[3]);
            }
        }
        __syncthreads();
    }

    // ---- store ----
    const float* bias = nullptr;
    if constexpr (MODE == 0)
        bias = (zb == 0) ? b0s : (zb == 1) ? b1s : (zb == 2) ? b2s : b3s;

    const int g8 = lane >> 2, t2 = (lane & 3) * 2;
    const int mb = m0 + wm * 16, nbb = n0 + wn * 48;

    if constexpr (MODE <= 2) {
        // pair-packed bf16 stores (even n; rows even-width so pairs never straddle)
        #pragma unroll
        for (int j = 0; j < 6; j++) {
            #pragma unroll
            for (int h = 0; h < 2; h++) {
                const int m = mb + g8 + h * 8;
                const int n = nbb + j * 8 + t2;          // even
                const float v0 = acc[j][2 * h], v1 = acc[j][2 * h + 1];
                if constexpr (MODE == 0) {
                    if (n + 1 < DTP) {
                        float a0 = (n < DT) ? v0 + bias[n] : 0.f;
                        float a1 = (n + 1 < DT) ? v1 + bias[n + 1] : 0.f;
                        store_pair(g_ph[zb], g_pl[zb], (size_t)m * DTP + n, a0, a1);
                    }
                }
                if constexpr (MODE == 1) {
                    if (n < NFLAT) {
                        int oi = n / DT, jj = n - oi * DT;
                        int o = oi / DT, i = oi - o * DT;
                        size_t d = ((size_t)(m * NOUT + o) * DT + i) * DTP + jj;
                        store_pair(g_wh, g_wl, d, v0, v1);
                    }
                }
                if constexpr (MODE == 2) {
                    int qq = n / DT, i = n - qq * DT;
                    size_t d = ((size_t)(zb * 576 + qq) * LLn + m) * DTP + i;
                    store_pair(g_th, g_tl, d, v0, v1);
                }
            }
        }
    } else {
        #pragma unroll
        for (int j = 0; j < 6; j++) {
            #pragma unroll
            for (int e = 0; e < 4; e++) {
                const int m = mb + g8 + ((e >> 1) ? 8 : 0);
                const int n = nbb + j * 8 + t2 + (e & 1);
                const float v = acc[j][e];
                int qq = n / LLn, y = n - qq * LLn;
                int z = qq >> 2, o = qq & 3;
                if constexpr (MODE == 3) {
                    if (z <= m) {
                        size_t bz = (size_t)zb * LLn + z;
                        outp[((bz * LLn + m) * LLn + y) * NOUT + o] = v;
                    }
                }
                if constexpr (MODE == 4) {
                    if (z <= y) {
                        size_t bz = (size_t)zb * LLn + z;
                        outp[((bz * LLn + y) * LLn + m) * NOUT + o] = v;
                    }
                }
            }
        }
    }
}

// ---------------- epilogue: mask + log_softmax over NOUT=4 ----------------
__global__ void epilogue_kernel(float* __restrict__ out)
{
    int e = blockIdx.x * blockDim.x + threadIdx.x;
    if (e >= TOT4) return;
    int rr = e % PEROUT;
    int x = (rr / LLn) % LLn;
    int z = (rr / (LLn * LLn)) % LLn;

    float4* p4 = (float4*)out;
    if (z > x) {
        const float c = -1.3862943611198906f;
        p4[e] = make_float4(c, c, c, c);
    } else {
        float4 v = p4[e];
        float m = fmaxf(fmaxf(v.x, v.y), fmaxf(v.z, v.w));
        float s = expf(v.x - m) + expf(v.y - m) + expf(v.z - m) + expf(v.w - m);
        float l = m + logf(s);
        v.x -= l; v.y -= l; v.z -= l; v.w -= l;
        p4[e] = v;
    }
}

// ---------------------------------------------------------------------------
extern "C" void kernel_launch(void* const* d_in, const int* in_sizes, int n_in,
                              void* d_out, int out_size)
{
    const float* x     = (const float*)d_in[0];
    const float* W_sh  = (const float*)d_in[1];
    const float* b_sh  = (const float*)d_in[2];
    const float* W_st  = (const float*)d_in[3];
    const float* b_st  = (const float*)d_in[4];
    const float* W_oh  = (const float*)d_in[5];
    const float* b_oh  = (const float*)d_in[6];
    const float* W_ot  = (const float*)d_in[7];
    const float* b_ot  = (const float*)d_in[8];
    const float* W_t1  = (const float*)d_in[9];
    const float* W_t2  = (const float*)d_in[10];
    float* out = (float*)d_out;

    // prep: split inputs/weights into bf16 hi/lo
    prep_x<<<(BL * DIN + 255) / 256, 256>>>(x);
    prep_pw<<<(DT * DIN + 255) / 256, 256>>>(W_sh, 0);
    prep_pw<<<(DT * DIN + 255) / 256, 256>>>(W_st, 1);
    prep_pw<<<(DT * DIN + 255) / 256, 256>>>(W_oh, 2);
    prep_pw<<<(DT * DIN + 255) / 256, 256>>>(W_ot, 3);
    prep_wt<<<dim3(OI, 5, 5), dim3(32, 32)>>>(W_t1, 0);
    prep_wt<<<dim3(OI, 5, 5), dim3(32, 32)>>>(W_t2, 1);

    // projections: M=288 (6 tiles) x N=150 (2 tiles of 96) x 4 sel
    tk<0><<<dim3(6, 2, 4), 192>>>(b_sh, b_st, b_oh, b_ot, nullptr, 0, 0);

    // triaffine 1: (x=st[1], y=oh[2], z=sh[0], W1)
    tk<1><<<dim3(6, 938, 1), 192>>>(nullptr, nullptr, nullptr, nullptr, nullptr, 0, 0);
    tk<2><<<dim3(3, 900, 2), 192>>>(nullptr, nullptr, nullptr, nullptr, nullptr, 2, 0);
    tk<3><<<dim3(3, 864, 2), 192>>>(nullptr, nullptr, nullptr, nullptr, out, 1, 0);

    // triaffine 2: (x=ot[3], y=st[1], z=sh[0], W2), transposed final coords
    tk<1><<<dim3(6, 938, 1), 192>>>(nullptr, nullptr, nullptr, nullptr, nullptr, 0, 1);
    tk<2><<<dim3(3, 900, 2), 192>>>(nullptr, nullptr, nullptr, nullptr, nullptr, 1, 0);
    tk<4><<<dim3(3, 864, 2), 192>>>(nullptr, nullptr, nullptr, nullptr, out + OUT1N, 3, 0);

    // mask + log_softmax
    epilogue_kernel<<<(TOT4 + 255) / 256, 256>>>(out);
}

// round 7
// speedup vs baseline: 2.7206x; 1.0743x over previous
#include <cuda_runtime.h>
#include <cuda_bf16.h>
#include <math.h>
#include <stdint.h>

// ---------------- problem constants ----------------
#define LLn   144
#define DIN   1024
#define DT    150
#define DTP   160
#define NOUT  4
#define BL    288
#define BZO   1152
#define OI    600
#define NFLAT 90000          // OI*DT      (flattened op1 N)
#define NF2   86400          // 576*DT     (flattened op2 N per batch)
#define NF3   82944          // 576*LLn    (flattened op3 N per batch)
#define OUT1N 23887872
#define LOGQ  -1.3862943611198906f

// ---------------- scratch (device globals, bf16 hi/lo splits) -------------
// pad columns [150,160) of g_w / g_t are never written -> stay zero (load-time
// zero-init), which is exactly what the K=160 consumers need.
__device__ __align__(256) __nv_bfloat16 g_xh[BL*DIN],        g_xl[BL*DIN];
__device__ __align__(256) __nv_bfloat16 g_Wph[4][DT*DIN],    g_Wpl[4][DT*DIN];   // [sel][n][k]
__device__ __align__(256) __nv_bfloat16 g_Wth[2][OI*DT*DTP], g_Wtl[2][OI*DT*DTP];// [tri][(oi,j)][k]
__device__ __align__(256) __nv_bfloat16 g_ph[4][BL*DTP],     g_pl[4][BL*DTP];
__device__ __align__(256) __nv_bfloat16 g_wh[(size_t)BZO*DT*DTP],  g_wl[(size_t)BZO*DT*DTP];
// g_t rows per batch: (z*144+y)*4+o  (o innermost -> softmax quads adjacent)
__device__ __align__(256) __nv_bfloat16 g_th[(size_t)BZO*LLn*DTP], g_tl[(size_t)BZO*LLn*DTP];

// ---------------- helpers ----------------
__device__ __forceinline__ void split2(float v, __nv_bfloat16& h, __nv_bfloat16& l) {
    h = __float2bfloat16_rn(v);
    l = __float2bfloat16_rn(v - __bfloat162float(h));
}
__device__ __forceinline__ void store_pair(__nv_bfloat16* baseH, __nv_bfloat16* baseL,
                                           size_t d, float v0, float v1) {
    __nv_bfloat16 h0, l0, h1, l1;
    split2(v0, h0, l0);
    split2(v1, h1, l1);
    uint32_t ph = (uint32_t)__bfloat16_as_ushort(h0) | ((uint32_t)__bfloat16_as_ushort(h1) << 16);
    uint32_t pl = (uint32_t)__bfloat16_as_ushort(l0) | ((uint32_t)__bfloat16_as_ushort(l1) << 16);
    *(uint32_t*)(baseH + d) = ph;
    *(uint32_t*)(baseL + d) = pl;
}
__device__ __forceinline__ uint32_t smem_u32(const void* p) {
    uint32_t a;
    asm("{ .reg .u64 t; cvta.to.shared.u64 t, %1; cvt.u32.u64 %0, t; }" : "=r"(a) : "l"(p));
    return a;
}
__device__ __forceinline__ void ldm4(uint32_t* d, uint32_t addr) {
    asm volatile("ldmatrix.sync.aligned.m8n8.x4.shared.b16 {%0,%1,%2,%3}, [%4];"
        : "=r"(d[0]), "=r"(d[1]), "=r"(d[2]), "=r"(d[3]) : "r"(addr));
}
__device__ __forceinline__ void mma_bf16(float* c, const uint32_t* a, uint32_t b0, uint32_t b1) {
    asm volatile("mma.sync.aligned.m16n8k16.row.col.f32.bf16.bf16.f32 "
        "{%0,%1,%2,%3}, {%4,%5,%6,%7}, {%8,%9}, {%0,%1,%2,%3};"
        : "+f"(c[0]), "+f"(c[1]), "+f"(c[2]), "+f"(c[3])
        : "r"(a[0]), "r"(a[1]), "r"(a[2]), "r"(a[3]), "r"(b0), "r"(b1));
}
__device__ __forceinline__ void cpa16(uint32_t dst, const void* src, uint32_t sz) {
    asm volatile("cp.async.cg.shared.global [%0], [%1], 16, %2;"
        :: "r"(dst), "l"(src), "r"(sz) : "memory");
}
__device__ __forceinline__ float4 lsm4(float a, float b, float c, float d) {
    float m = fmaxf(fmaxf(a, b), fmaxf(c, d));
    float s = expf(a - m) + expf(b - m) + expf(c - m) + expf(d - m);
    float l = m + logf(s);
    return make_float4(a - l, b - l, c - l, d - l);
}

// ---------------- prep kernels ----------------
__global__ void prep_x(const float* __restrict__ x) {
    int i = blockIdx.x * 256 + threadIdx.x;
    if (i >= BL * DIN) return;
    split2(x[i], g_xh[i], g_xl[i]);
}
__global__ void prep_pw4(const float* __restrict__ W0, const float* __restrict__ W1,
                         const float* __restrict__ W2, const float* __restrict__ W3) {
    int i = blockIdx.x * 256 + threadIdx.x;
    if (i >= DT * DIN) return;
    int sel = blockIdx.y;
    const float* W = (sel == 0) ? W0 : (sel == 1) ? W1 : (sel == 2) ? W2 : W3;
    int n = i >> 10, k = i & 1023;
    split2(__ldg(&W[k * DT + n]), g_Wph[sel][i], g_Wpl[sel][i]);
}
__global__ void prep_wt2(const float* __restrict__ Wa, const float* __restrict__ Wb) {
    __shared__ float t[32][33];
    int oi = blockIdx.x;
    int tri = blockIdx.z;
    const float* W = tri ? Wb : Wa;
    int kt = (blockIdx.y / 5) * 32, jt = (blockIdx.y % 5) * 32;
    int tx = threadIdx.x, ty = threadIdx.y;
    int k = kt + ty, j = jt + tx;
    float v = (k < DT && j < DT) ? W[(size_t)oi * (DT * DT) + k * DT + j] : 0.f;
    t[ty][tx] = v;
    __syncthreads();
    int j2 = jt + ty, k2 = kt + tx;
    if (j2 < DT && k2 < DTP) {
        float u = t[tx][ty];
        size_t d = (size_t)oi * (DT * DTP) + (size_t)j2 * DTP + k2;
        split2(u, g_Wth[tri][d], g_Wtl[tri][d]);
    }
}

// ---------------- HMMA GEMM: BM=48, BN=96, BK=32, 192 thr, double-buffered -
// MODE 0: proj   x(288x1024) @ Wp[z](as [n][k]) -> g_p[z]   (z=blockIdx.z)
// MODE 1: op1    sh(288xDTP) @ Wt[tri] flat N=90000 -> g_w
// MODE 2: op2    Y_b(144xDTP) @ g_w[b] flat N=86400 -> g_t (o-innermost rows)
// MODE 3: op3/1  X_b(144xDTP) @ g_t[b] flat N=82944 -> out, fused logsoftmax
// MODE 4: op3/2  same, transposed final coords, fused logsoftmax
#define STG    23040
#define OFF_AL 3840
#define OFF_BH 7680
#define OFF_BL 15360
#define NIT    6            // 1152 segments / 192 threads

template<int MODE>
__global__ __launch_bounds__(192)
void tk(const float* __restrict__ b0s, const float* __restrict__ b1s,
        const float* __restrict__ b2s, const float* __restrict__ b3s,
        float* __restrict__ outp, int sel, int tri)
{
    __shared__ __align__(16) char sm[2][STG];

    const int tid  = threadIdx.x;
    const int lane = tid & 31, warp = tid >> 5;
    const int wm = warp >> 1, wn = warp & 1;
    const int bx = blockIdx.x, by = blockIdx.y, zb = blockIdx.z;
    const int m0 = bx * 48, n0 = by * 96;

    // ---- fully-masked block: fill constants, skip GEMM ----
    if constexpr (MODE == 3 || MODE == 4) {
        bool allmask;
        if constexpr (MODE == 3) {
            allmask = ((n0 >> 2) / LLn) > (m0 + 47);
        } else {
            allmask = true;
            #pragma unroll 1
            for (int qd = 0; qd < 24; qd++) {
                int nq = (n0 >> 2) + qd;
                if (nq / LLn <= nq % LLn) { allmask = false; break; }
            }
        }
        if (allmask) {
            const float4 c4 = make_float4(LOGQ, LOGQ, LOGQ, LOGQ);
            for (int idx = tid; idx < 48 * 24; idx += 192) {
                int mm = m0 + idx / 24;
                int nq = (n0 >> 2) + idx % 24;
                int z = nq / LLn, t = nq % LLn;
                size_t qb;
                if constexpr (MODE == 3)
                    qb = (((size_t)(zb * LLn + z) * LLn + mm) * LLn + t);
                else
                    qb = (((size_t)(zb * LLn + z) * LLn + t) * LLn + mm);
                ((float4*)outp)[qb] = c4;
            }
            return;
        }
    }

    const __nv_bfloat16 *Ah, *Al, *Bh, *Bl;
    int pitchA, pitchB, KT, NB;
    if constexpr (MODE == 0) {
        Ah = g_xh; Al = g_xl; Bh = g_Wph[zb]; Bl = g_Wpl[zb];
        pitchA = DIN; pitchB = DIN; KT = 32; NB = DT;
    }
    if constexpr (MODE == 1) {
        Ah = g_ph[0]; Al = g_pl[0]; Bh = g_Wth[tri]; Bl = g_Wtl[tri];
        pitchA = DTP; pitchB = DTP; KT = 5; NB = NFLAT;
    }
    if constexpr (MODE == 2) {
        Ah = g_ph[sel] + (size_t)zb * LLn * DTP; Al = g_pl[sel] + (size_t)zb * LLn * DTP;
        Bh = g_wh + (size_t)zb * 576 * DT * DTP; Bl = g_wl + (size_t)zb * 576 * DT * DTP;
        pitchA = DTP; pitchB = DTP; KT = 5; NB = NF2;
    }
    if constexpr (MODE >= 3) {
        Ah = g_ph[sel] + (size_t)zb * LLn * DTP; Al = g_pl[sel] + (size_t)zb * LLn * DTP;
        Bh = g_th + (size_t)zb * NF3 * DTP;      Bl = g_tl + (size_t)zb * NF3 * DTP;
        pitchA = DTP; pitchB = DTP; KT = 5; NB = NF3;
    }

    const uint32_t sbase = smem_u32(sm);

    // ---- precompute per-thread staging plan: NIT segments of 16B ----
    const __nv_bfloat16* sptr[NIT];
    uint32_t sdst[NIT], ssz[NIT];
    #pragma unroll
    for (int it = 0; it < NIT; it++) {
        int idx = tid + it * 192;                    // 0..1151
        if (idx < 384) {
            int mat = idx / 192;                     // 0=Ah 1=Al
            int rem = idx - mat * 192;
            int row = rem >> 2, seg = rem & 3;
            sptr[it] = (mat ? Al : Ah) + (size_t)(m0 + row) * pitchA + seg * 8;
            sdst[it] = (uint32_t)(mat * OFF_AL + row * 80 + seg * 16);
            ssz[it]  = 16;
        } else {
            int rem = idx - 384;                     // 0..767
            int mat = (rem < 384) ? 0 : 1;           // 0=Bh 1=Bl
            int brem = (rem < 384) ? rem : rem - 384;
            int row = brem >> 2, seg = brem & 3;
            int gr = n0 + row;
            bool vv = gr < NB;
            sptr[it] = ((mat == 1) ? Bl : Bh) + (size_t)(vv ? gr : n0) * pitchB + seg * 8;
            sdst[it] = (uint32_t)(OFF_BH + mat * 7680 + row * 80 + seg * 16);
            ssz[it]  = vv ? 16u : 0u;
        }
    }

    // ---- ldmatrix lane offsets (pitch-80 rows, conflict-free) ----
    const int q = lane >> 3, r = lane & 7;
    const uint32_t aOff  = (uint32_t)((wm * 16 + ((q & 1) ? 8 : 0) + r) * 80 + ((q >> 1) ? 16 : 0));
    const uint32_t bOff0 = (uint32_t)((wn * 48 + ((lane >> 4) ? 8 : 0) + r) * 80 + ((q & 1) ? 16 : 0));

    float acc[6][4];
    #pragma unroll
    for (int i = 0; i < 6; i++)
        #pragma unroll
        for (int j = 0; j < 4; j++) acc[i][j] = 0.f;

    auto stageCh = [&](int buf) {
        const uint32_t sb = sbase + (uint32_t)(buf * STG);
        #pragma unroll
        for (int it = 0; it < NIT; it++) {
            cpa16(sb + sdst[it], sptr[it], ssz[it]);
            sptr[it] += 32;
        }
        asm volatile("cp.async.commit_group;" ::: "memory");
    };

    stageCh(0);

    for (int ch = 0; ch < KT; ch++) {
        if (ch + 1 < KT) {
            stageCh((ch + 1) & 1);
            asm volatile("cp.async.wait_group 1;" ::: "memory");
        } else {
            asm volatile("cp.async.wait_group 0;" ::: "memory");
        }
        __syncthreads();

        const uint32_t cb = sbase + (uint32_t)((ch & 1) * STG);
        #pragma unroll
        for (int ks = 0; ks < 2; ks++) {
            const uint32_t ko = (uint32_t)(ks * 32);
            uint32_t ah[4], al4[4];
            ldm4(ah,  cb + aOff + ko);
            ldm4(al4, cb + OFF_AL + aOff + ko);
            #pragma unroll
            for (int g = 0; g < 3; g++) {
                uint32_t bh[4], bl[4];
                const uint32_t bo = bOff0 + (uint32_t)(g * 1280) + ko;
                ldm4(bh, cb + OFF_BH + bo);
                ldm4(bl, cb + OFF_BL + bo);
                mma_bf16(acc[2 * g],     ah,  bh[0], bh[1]);
                mma_bf16(acc[2 * g],     ah,  bl[0], bl[1]);
                mma_bf16(acc[2 * g],     al4, bh[0], bh[1]);
                mma_bf16(acc[2 * g + 1], ah,  bh[2], bh[3]);
                mma_bf16(acc[2 * g + 1], ah,  bl[2], bl[3]);
                mma_bf16(acc[2 * g + 1], al4, bh[2], bh[3]);
            }
        }
        __syncthreads();
    }

    // ---- store ----
    const float* bias = nullptr;
    if constexpr (MODE == 0)
        bias = (zb == 0) ? b0s : (zb == 1) ? b1s : (zb == 2) ? b2s : b3s;

    const int g8 = lane >> 2, cc = lane & 3, t2 = cc * 2;
    const int mb = m0 + wm * 16, nbb = n0 + wn * 48;

    if constexpr (MODE <= 2) {
        // pair-packed bf16 stores (even n; rows even-width so pairs never straddle)
        #pragma unroll
        for (int j = 0; j < 6; j++) {
            #pragma unroll
            for (int h = 0; h < 2; h++) {
                const int m = mb + g8 + h * 8;
                const int n = nbb + j * 8 + t2;          // even
                const float v0 = acc[j][2 * h], v1 = acc[j][2 * h + 1];
                if constexpr (MODE == 0) {
                    if (n + 1 < DTP) {
                        float a0 = (n < DT) ? v0 + bias[n] : 0.f;
                        float a1 = (n + 1 < DT) ? v1 + bias[n + 1] : 0.f;
                        store_pair(g_ph[zb], g_pl[zb], (size_t)m * DTP + n, a0, a1);
                    }
                }
                if constexpr (MODE == 1) {
                    if (n < NFLAT) {
                        int oi = n / DT, jj = n - oi * DT;
                        int o = oi / DT, i = oi - o * DT;
                        size_t d = ((size_t)(m * NOUT + o) * DT + i) * DTP + jj;
                        store_pair(g_wh, g_wl, d, v0, v1);
                    }
                }
                if constexpr (MODE == 2) {
                    int qq = n / DT, i = n - qq * DT;
                    int z = qq >> 2, o = qq & 3;
                    // o-innermost t layout: row (z*144+y)*4+o
                    size_t rrow = ((size_t)(z * LLn + m)) * NOUT + o;
                    size_t d = ((size_t)zb * NF3 + rrow) * DTP + i;
                    store_pair(g_th, g_tl, d, v0, v1);
                }
            }
        }
    } else {
        // fused mask + log_softmax; one float4 per quad, even-cc lanes store
        #pragma unroll
        for (int j = 0; j < 6; j++) {
            #pragma unroll
            for (int h = 0; h < 2; h++) {
                const float a0 = acc[j][2 * h], a1 = acc[j][2 * h + 1];
                const float p0 = __shfl_xor_sync(0xffffffffu, a0, 1);
                const float p1 = __shfl_xor_sync(0xffffffffu, a1, 1);
                if (!(cc & 1)) {
                    const int nq = (nbb + j * 8 + ((cc == 2) ? 4 : 0)) >> 2;
                    const int z = nq / LLn, t = nq - z * LLn;
                    const int m = mb + g8 + h * 8;
                    const bool keep = (MODE == 3) ? (z <= m) : (z <= t);
                    float4 r4;
                    if (keep) r4 = lsm4(a0, a1, p0, p1);
                    else      r4 = make_float4(LOGQ, LOGQ, LOGQ, LOGQ);
                    size_t qb;
                    if constexpr (MODE == 3)
                        qb = (((size_t)(zb * LLn + z) * LLn + m) * LLn + t);
                    else
                        qb = (((size_t)(zb * LLn + z) * LLn + t) * LLn + m);
                    ((float4*)outp)[qb] = r4;
                }
            }
        }
    }
}

// ---------------------------------------------------------------------------
extern "C" void kernel_launch(void* const* d_in, const int* in_sizes, int n_in,
                              void* d_out, int out_size)
{
    const float* x     = (const float*)d_in[0];
    const float* W_sh  = (const float*)d_in[1];
    const float* b_sh  = (const float*)d_in[2];
    const float* W_st  = (const float*)d_in[3];
    const float* b_st  = (const float*)d_in[4];
    const float* W_oh  = (const float*)d_in[5];
    const float* b_oh  = (const float*)d_in[6];
    const float* W_ot  = (const float*)d_in[7];
    const float* b_ot  = (const float*)d_in[8];
    const float* W_t1  = (const float*)d_in[9];
    const float* W_t2  = (const float*)d_in[10];
    float* out = (float*)d_out;

    // prep: split inputs/weights into bf16 hi/lo
    prep_x<<<(BL * DIN + 255) / 256, 256>>>(x);
    prep_pw4<<<dim3((DT * DIN + 255) / 256, 4), 256>>>(W_sh, W_st, W_oh, W_ot);
    prep_wt2<<<dim3(OI, 25, 2), dim3(32, 32)>>>(W_t1, W_t2);

    // projections: M=288 (6 tiles) x N=150 (2 tiles of 96) x 4 sel
    tk<0><<<dim3(6, 2, 4), 192>>>(b_sh, b_st, b_oh, b_ot, nullptr, 0, 0);

    // triaffine 1: (x=st[1], y=oh[2], z=sh[0], W1)
    tk<1><<<dim3(6, 938, 1), 192>>>(nullptr, nullptr, nullptr, nullptr, nullptr, 0, 0);
    tk<2><<<dim3(3, 900, 2), 192>>>(nullptr, nullptr, nullptr, nullptr, nullptr, 2, 0);
    tk<3><<<dim3(3, 864, 2), 192>>>(nullptr, nullptr, nullptr, nullptr, out, 1, 0);

    // triaffine 2: (x=ot[3], y=st[1], z=sh[0], W2), transposed final coords
    tk<1><<<dim3(6, 938, 1), 192>>>(nullptr, nullptr, nullptr, nullptr, nullptr, 0, 1);
    tk<2><<<dim3(3, 900, 2), 192>>>(nullptr, nullptr, nullptr, nullptr, nullptr, 1, 0);
    tk<4><<<dim3(3, 864, 2), 192>>>(nullptr, nullptr, nullptr, nullptr, out + OUT1N, 3, 0);
}